// round 2
// baseline (speedup 1.0000x reference)
#include <cuda_runtime.h>

// PowerSpectrum: per environment j (8192), per degree l (0..6):
//   G_l = S_l S_l^T / sqrt(2l+1),  S_l: [64, 2l+1]
//   features: diag(G) (64) ++ sqrt(2)*triu(G,1) (2016), concat over l -> 14560
//   output = features / max(||features||_2, 1e-12)
//
// One CTA per j. se staged in smem (rows padded to 4-float multiples).
// 952 tile-tasks = 7 l * 136 upper-tri 4x4 blocks of the 16x16 tile grid.
// Each thread owns <=4 tiles; accumulators stay in registers through the
// norm reduction, then get scaled and streamed to gmem.

#define NJ      8192
#define NA      64
#define NL      7
#define FEAT_L  2080
#define NDIM    14560
#define NTILE   16
#define TILES_L 136
#define NTASK   (NL * TILES_L)   // 952
#define NTHREADS 256
#define MAXIT   4                // ceil(952/256)

__global__ __launch_bounds__(NTHREADS, 2)
void powerspectrum_kernel(const float* __restrict__ se0,
                          const float* __restrict__ se1,
                          const float* __restrict__ se2,
                          const float* __restrict__ se3,
                          const float* __restrict__ se4,
                          const float* __restrict__ se5,
                          const float* __restrict__ se6,
                          float* __restrict__ out)
{
    // Kpad per l: 4,4,8,8,12,12,16 ; row-major [a][k] per l, cum offsets:
    const int   SOFF[NL] = {0, 256, 512, 1024, 1536, 2304, 3072};
    const float RSQ[NL]  = {1.0f, 0.57735026918962576f, 0.44721359549995794f,
                            0.37796447300922722f, 0.33333333333333333f,
                            0.30151134457776363f, 0.27735009811261457f};
    const float SQRT2 = 1.4142135623730951f;

    __shared__ float S[4096];     // 16 KB staged se (zero-padded rows)
    __shared__ float red[NTHREADS];

    const int j   = blockIdx.x;
    const int tid = threadIdx.x;

    // ---- zero smem (padding lanes must be 0 so padded dots are exact) ----
    #pragma unroll
    for (int i = tid; i < 4096; i += NTHREADS) S[i] = 0.0f;
    __syncthreads();

    // ---- stage inputs into smem with row padding ----
    const float* ses[NL] = {se0, se1, se2, se3, se4, se5, se6};
    #pragma unroll
    for (int l = 0; l < NL; ++l) {
        const int K    = 2 * l + 1;
        const int Kpad = (K + 3) & ~3;
        const int soff = SOFF[l];
        const float* g = ses[l] + (size_t)j * (NA * K);
        for (int idx = tid; idx < NA * K; idx += NTHREADS) {
            int a = idx / K;           // K is compile-time per unrolled l
            int k = idx - a * K;
            S[soff + a * Kpad + k] = g[idx];
        }
    }
    __syncthreads();

    // ---- compute 4x4 Gram tiles in registers ----
    float acc[MAXIT][16];
    int   tl[MAXIT], tta[MAXIT], ttb[MAXIT];
    float partial = 0.0f;

    #pragma unroll
    for (int it = 0; it < MAXIT; ++it) {
        tl[it] = -1;
        int task = tid + it * NTHREADS;
        if (task >= NTASK) continue;

        int l = task / TILES_L;
        int t = task - l * TILES_L;
        int ta = 0;
        while (t >= NTILE - ta) { t -= NTILE - ta; ++ta; }
        int tb = ta + t;
        tl[it] = l; tta[it] = ta; ttb[it] = tb;

        const int K    = 2 * l + 1;
        const int Kpad = (K + 3) & ~3;
        const float* Sa = &S[SOFF[l] + ta * 4 * Kpad];
        const float* Sb = &S[SOFF[l] + tb * 4 * Kpad];

        #pragma unroll
        for (int i = 0; i < 16; ++i) acc[it][i] = 0.0f;

        for (int k4 = 0; k4 < Kpad; k4 += 4) {
            float4 ar[4], br[4];
            #pragma unroll
            for (int r = 0; r < 4; ++r)
                ar[r] = *(const float4*)(Sa + r * Kpad + k4);
            #pragma unroll
            for (int c = 0; c < 4; ++c)
                br[c] = *(const float4*)(Sb + c * Kpad + k4);
            #pragma unroll
            for (int r = 0; r < 4; ++r)
                #pragma unroll
                for (int c = 0; c < 4; ++c)
                    acc[it][r * 4 + c] += ar[r].x * br[c].x + ar[r].y * br[c].y
                                        + ar[r].z * br[c].z + ar[r].w * br[c].w;
        }

        // sum-of-squares contribution (feature scaling folded in):
        //   diag feature  = dot * RSQ[l]          -> dot^2 / (2l+1)
        //   off  feature  = dot * RSQ[l] * sqrt2  -> 2*dot^2 / (2l+1)
        const float inv2l1 = RSQ[l] * RSQ[l];
        if (ta < tb) {
            float s = 0.0f;
            #pragma unroll
            for (int i = 0; i < 16; ++i) s += acc[it][i] * acc[it][i];
            partial += 2.0f * inv2l1 * s;
        } else {
            float s = 0.0f;
            #pragma unroll
            for (int r = 0; r < 4; ++r)
                #pragma unroll
                for (int c = 0; c < 4; ++c) {
                    float v = acc[it][r * 4 + c];
                    if (c > r)       s += 2.0f * v * v;
                    else if (c == r) s += v * v;
                }
            partial += inv2l1 * s;
        }
    }

    // ---- block reduction of ||PS||^2 ----
    red[tid] = partial;
    __syncthreads();
    #pragma unroll
    for (int s = NTHREADS / 2; s > 0; s >>= 1) {
        if (tid < s) red[tid] += red[tid + s];
        __syncthreads();
    }
    const float norm = fmaxf(sqrtf(red[0]), 1e-12f);
    const float invn = 1.0f / norm;

    // ---- scale + scatter to gmem ----
    float* op = out + (size_t)j * NDIM;
    #pragma unroll
    for (int it = 0; it < MAXIT; ++it) {
        int l = tl[it];
        if (l < 0) continue;
        int ta = tta[it], tb = ttb[it];
        float sl = RSQ[l] * invn;
        float so = sl * SQRT2;
        float* ob = op + l * FEAT_L;

        if (ta < tb) {
            #pragma unroll
            for (int r = 0; r < 4; ++r) {
                int a  = ta * 4 + r;
                int p0 = a * (127 - a) / 2 + (tb * 4 - a - 1);  // triu index of (a, tb*4)
                #pragma unroll
                for (int c = 0; c < 4; ++c)
                    ob[64 + p0 + c] = acc[it][r * 4 + c] * so;
            }
        } else {  // diagonal tile: r==c -> diag region, r<c -> off-diag region
            #pragma unroll
            for (int r = 0; r < 4; ++r) {
                int a = ta * 4 + r;
                #pragma unroll
                for (int c = 0; c < 4; ++c) {
                    int b = tb * 4 + c;
                    float v = acc[it][r * 4 + c];
                    if (c == r) {
                        ob[a] = v * sl;
                    } else if (c > r) {
                        ob[64 + a * (127 - a) / 2 + (b - a - 1)] = v * so;
                    }
                }
            }
        }
    }
}

extern "C" void kernel_launch(void* const* d_in, const int* in_sizes, int n_in,
                              void* d_out, int out_size)
{
    const float* se0 = (const float*)d_in[0];
    const float* se1 = (const float*)d_in[1];
    const float* se2 = (const float*)d_in[2];
    const float* se3 = (const float*)d_in[3];
    const float* se4 = (const float*)d_in[4];
    const float* se5 = (const float*)d_in[5];
    const float* se6 = (const float*)d_in[6];
    float* out = (float*)d_out;

    powerspectrum_kernel<<<NJ, NTHREADS>>>(se0, se1, se2, se3, se4, se5, se6, out);
}

// round 4
// speedup vs baseline: 1.3853x; 1.3853x over previous
#include <cuda_runtime.h>

// PowerSpectrum: per environment j (8192), per degree l (0..6):
//   G_l = S_l S_l^T / sqrt(2l+1),  S_l: [64, 2l+1]
//   features: diag(G) (64) ++ sqrt(2)*triu(G,1) (2016), concat over l -> 14560
//   output = features / max(||features||_2, 1e-12)
//
// R3: one CTA per j. Inputs staged in smem (rows padded to 4-float multiples).
// 952 tile-tasks = 7 l * 136 upper-tri 4x4 blocks of the 16x16 tile grid.
// Each tile's pre-norm feature values are scattered into a smem feature
// buffer (cheap), sum-of-squares block-reduced, then the whole 14560-float
// row is streamed to gmem as coalesced float4 stores scaled by 1/norm.

#define NJ      8192
#define NA      64
#define NL      7
#define FEAT_L  2080
#define NDIM    14560
#define NTILE   16
#define TILES_L 136
#define NTASK   (NL * TILES_L)   // 952
#define NTHREADS 256
#define MAXIT   4                // ceil(952/256)

#define S_FLOATS 4096
#define SMEM_BYTES ((S_FLOATS + NDIM) * 4)   // 74624

__global__ __launch_bounds__(NTHREADS)
void powerspectrum_kernel(const float* __restrict__ se0,
                          const float* __restrict__ se1,
                          const float* __restrict__ se2,
                          const float* __restrict__ se3,
                          const float* __restrict__ se4,
                          const float* __restrict__ se5,
                          const float* __restrict__ se6,
                          float* __restrict__ out)
{
    // Kpad per l: 4,4,8,8,12,12,16 ; row-major [a][k] per l, cum offsets:
    const int   SOFF[NL] = {0, 256, 512, 1024, 1536, 2304, 3072};
    const float RSQ[NL]  = {1.0f, 0.57735026918962576f, 0.44721359549995794f,
                            0.37796447300922722f, 0.33333333333333333f,
                            0.30151134457776363f, 0.27735009811261457f};
    const float SQRT2 = 1.4142135623730951f;

    extern __shared__ float dyn[];
    float* S = dyn;               // [4096] staged se (zero-padded rows)
    float* F = dyn + S_FLOATS;    // [14560] pre-norm feature buffer
    __shared__ float red[NTHREADS];

    const int j   = blockIdx.x;
    const int tid = threadIdx.x;

    // ---- zero input staging (padding lanes must be 0 for exact padded dots) ----
    #pragma unroll
    for (int i = tid; i < S_FLOATS; i += NTHREADS) S[i] = 0.0f;
    __syncthreads();

    // ---- stage inputs into smem with row padding ----
    const float* ses[NL] = {se0, se1, se2, se3, se4, se5, se6};
    #pragma unroll
    for (int l = 0; l < NL; ++l) {
        const int K    = 2 * l + 1;
        const int Kpad = (K + 3) & ~3;
        const int soff = SOFF[l];
        const float* g = ses[l] + (size_t)j * (NA * K);
        for (int idx = tid; idx < NA * K; idx += NTHREADS) {
            int a = idx / K;           // K compile-time per unrolled l
            int k = idx - a * K;
            S[soff + a * Kpad + k] = g[idx];
        }
    }
    __syncthreads();

    // ---- compute 4x4 Gram tiles; scatter pre-norm features to smem ----
    float partial = 0.0f;

    #pragma unroll
    for (int it = 0; it < MAXIT; ++it) {
        int task = tid + it * NTHREADS;
        if (task >= NTASK) continue;

        int l = task / TILES_L;
        int t = task - l * TILES_L;
        int ta = 0;
        while (t >= NTILE - ta) { t -= NTILE - ta; ++ta; }
        int tb = ta + t;

        const int K    = 2 * l + 1;
        const int Kpad = (K + 3) & ~3;
        const float* Sa = &S[SOFF[l] + ta * 4 * Kpad];
        const float* Sb = &S[SOFF[l] + tb * 4 * Kpad];

        float acc[16];
        #pragma unroll
        for (int i = 0; i < 16; ++i) acc[i] = 0.0f;

        for (int k4 = 0; k4 < Kpad; k4 += 4) {
            float4 ar[4], br[4];
            #pragma unroll
            for (int r = 0; r < 4; ++r)
                ar[r] = *(const float4*)(Sa + r * Kpad + k4);
            #pragma unroll
            for (int c = 0; c < 4; ++c)
                br[c] = *(const float4*)(Sb + c * Kpad + k4);
            #pragma unroll
            for (int r = 0; r < 4; ++r)
                #pragma unroll
                for (int c = 0; c < 4; ++c)
                    acc[r * 4 + c] += ar[r].x * br[c].x + ar[r].y * br[c].y
                                    + ar[r].z * br[c].z + ar[r].w * br[c].w;
        }

        // fold per-l scaling, scatter to smem feature buffer, accumulate sumsq
        const float sl = RSQ[l];
        const float so = sl * SQRT2;
        float* fb = F + l * FEAT_L;

        if (ta < tb) {
            #pragma unroll
            for (int r = 0; r < 4; ++r) {
                int a  = ta * 4 + r;
                int p0 = 64 + a * (127 - a) / 2 + (tb * 4 - a - 1);
                #pragma unroll
                for (int c = 0; c < 4; ++c) {
                    float v = acc[r * 4 + c] * so;
                    fb[p0 + c] = v;
                    partial += v * v;
                }
            }
        } else {  // diagonal tile: r==c -> diag region, r<c -> off-diag region
            #pragma unroll
            for (int r = 0; r < 4; ++r) {
                int a = ta * 4 + r;
                #pragma unroll
                for (int c = 0; c < 4; ++c) {
                    int b = tb * 4 + c;
                    if (c == r) {
                        float v = acc[r * 4 + c] * sl;
                        fb[a] = v;
                        partial += v * v;
                    } else if (c > r) {
                        float v = acc[r * 4 + c] * so;
                        fb[64 + a * (127 - a) / 2 + (b - a - 1)] = v;
                        partial += v * v;
                    }
                }
            }
        }
    }

    // ---- block reduction of ||PS||^2 ----
    red[tid] = partial;
    __syncthreads();
    #pragma unroll
    for (int s = NTHREADS / 2; s > 0; s >>= 1) {
        if (tid < s) red[tid] += red[tid + s];
        __syncthreads();
    }
    const float invn = 1.0f / fmaxf(sqrtf(red[0]), 1e-12f);

    // ---- coalesced float4 streaming write ----
    const float4* Fv = (const float4*)F;
    float4* ov = (float4*)(out + (size_t)j * NDIM);
    #pragma unroll 4
    for (int i = tid; i < NDIM / 4; i += NTHREADS) {
        float4 v = Fv[i];
        v.x *= invn; v.y *= invn; v.z *= invn; v.w *= invn;
        ov[i] = v;
    }
}

extern "C" void kernel_launch(void* const* d_in, const int* in_sizes, int n_in,
                              void* d_out, int out_size)
{
    const float* se0 = (const float*)d_in[0];
    const float* se1 = (const float*)d_in[1];
    const float* se2 = (const float*)d_in[2];
    const float* se3 = (const float*)d_in[3];
    const float* se4 = (const float*)d_in[4];
    const float* se5 = (const float*)d_in[5];
    const float* se6 = (const float*)d_in[6];
    float* out = (float*)d_out;

    cudaFuncSetAttribute(powerspectrum_kernel,
                         cudaFuncAttributeMaxDynamicSharedMemorySize, SMEM_BYTES);

    powerspectrum_kernel<<<NJ, NTHREADS, SMEM_BYTES>>>(se0, se1, se2, se3,
                                                       se4, se5, se6, out);
}

// round 5
// speedup vs baseline: 2.0903x; 1.5090x over previous
#include <cuda_runtime.h>

// PowerSpectrum, R5: k-major smem layout (conflict-free LDS), norm precomputed
// from the K x K Gram trick (||S S^T||_F = ||S^T S||_F), per-l-pair phased
// feature scatter -> small smem buffer -> coalesced float4 streaming stores.
//
// Per env j: for l = 0..6, G_l = S_l S_l^T / sqrt(2l+1), S_l: [64, 2l+1].
// features = concat_l [ diag(G_l) (64) ; sqrt(2) * triu(G_l,1) (2016) ]  (14560)
// out = features / max(||features||, 1e-12)

#define NJ       8192
#define NA       64
#define NL       7
#define FEAT_L   2080
#define NDIM     14560
#define NTILE    16
#define TILES_L  136
#define NTHREADS 256
#define STRIDE   68            // k-row stride in floats (bank-stagger + 16B align)

#define S_FLOATS 3332          // sum_l K*STRIDE = 49*68
#define F_FLOATS (2 * FEAT_L)  // double-l feature staging
#define SMEM_BYTES ((S_FLOATS + F_FLOATS) * 4)   // 29968

__global__ __launch_bounds__(NTHREADS, 4)
void powerspectrum_kernel(const float* __restrict__ se0,
                          const float* __restrict__ se1,
                          const float* __restrict__ se2,
                          const float* __restrict__ se3,
                          const float* __restrict__ se4,
                          const float* __restrict__ se5,
                          const float* __restrict__ se6,
                          float* __restrict__ out)
{
    const int   KS[NL]     = {1, 3, 5, 7, 9, 11, 13};
    const int   SOFF[NL]   = {0, 68, 272, 612, 1088, 1700, 2448};
    const float RSQ[NL]    = {1.0f, 0.57735026918962576f, 0.44721359549995794f,
                              0.37796447300922722f, 0.33333333333333333f,
                              0.30151134457776363f, 0.27735009811261457f};
    const float INV2L1[NL] = {1.0f, 0.33333333333333333f, 0.2f,
                              0.14285714285714285f, 0.11111111111111111f,
                              0.090909090909090909f, 0.076923076923076923f};
    // cumulative K*(K+1)/2 for the norm pair tasks
    const int PAIR_OFF[NL + 1] = {0, 1, 7, 22, 50, 95, 161, 252};
    const float SQRT2 = 1.4142135623730951f;

    extern __shared__ float dyn[];
    float* S = dyn;               // [3332] k-major staged se: S[SOFF[l]+k*68+a]
    float* F = dyn + S_FLOATS;    // [4160] per-phase feature staging (2 l's)
    __shared__ float red[NTHREADS];

    const int j   = blockIdx.x;
    const int tid = threadIdx.x;

    // ---- stage inputs (coalesced gmem read, k-major transposed smem write) --
    {
        const float* ses[NL] = {se0, se1, se2, se3, se4, se5, se6};
        #pragma unroll
        for (int l = 0; l < NL; ++l) {
            const int K    = KS[l];
            const int soff = SOFF[l];
            const float* g = ses[l] + (size_t)j * (NA * K);
            for (int idx = tid; idx < NA * K; idx += NTHREADS) {
                int a = idx / K;
                int k = idx - a * K;
                S[soff + k * STRIDE + a] = g[idx];
            }
        }
    }
    __syncthreads();

    // ---- norm via ||S^T S||_F^2: 252 (l,k1<=k2) dot tasks over a=0..63 ----
    float partial = 0.0f;
    if (tid < PAIR_OFF[NL]) {
        int l = 0;
        #pragma unroll
        for (int q = 1; q < NL; ++q)
            if (tid >= PAIR_OFF[q]) l = q;
        int t = tid - PAIR_OFF[l];
        const int K = KS[l];
        int k1 = 0;
        while (t >= K - k1) { t -= K - k1; ++k1; }
        int k2 = k1 + t;

        const float4* r1 = (const float4*)(S + SOFF[l] + k1 * STRIDE);
        const float4* r2 = (const float4*)(S + SOFF[l] + k2 * STRIDE);
        float dot = 0.0f;
        #pragma unroll
        for (int q = 0; q < NA / 4; ++q) {
            float4 x = r1[q], y = r2[q];
            dot += x.x * y.x + x.y * y.y + x.z * y.z + x.w * y.w;
        }
        float w = (k1 == k2 ? 1.0f : 2.0f) * INV2L1[l];
        partial = w * dot * dot;
    }
    red[tid] = partial;
    __syncthreads();
    #pragma unroll
    for (int s = NTHREADS / 2; s > 0; s >>= 1) {
        if (tid < s) red[tid] += red[tid + s];
        __syncthreads();
    }
    const float invn = 1.0f / fmaxf(sqrtf(red[0]), 1e-12f);

    // ---- feature phases: l-pairs {0,1},{2,3},{4,5},{6} ----
    float* op = out + (size_t)j * NDIM;

    #pragma unroll
    for (int p = 0; p < 4; ++p) {
        const int l0     = 2 * p;
        const int nl_p   = (p < 3) ? 2 : 1;
        const int ntask  = nl_p * TILES_L;

        // compute 4x4 Gram tiles, scatter scaled features into F
        for (int task = tid; task < ntask; task += NTHREADS) {
            int sel = (task >= TILES_L) ? 1 : 0;
            int l   = l0 + sel;
            int t   = task - sel * TILES_L;
            int ta  = 0;
            while (t >= NTILE - ta) { t -= NTILE - ta; ++ta; }
            int tb = ta + t;

            const int K = KS[l];
            const float* Sl = S + SOFF[l];

            float acc[16];
            #pragma unroll
            for (int i = 0; i < 16; ++i) acc[i] = 0.0f;

            const float* pk = Sl;
            for (int k = 0; k < K; ++k, pk += STRIDE) {
                float4 A = *(const float4*)(pk + ta * 4);   // warp broadcast
                float4 B = *(const float4*)(pk + tb * 4);   // conflict-free
                acc[ 0] += A.x * B.x; acc[ 1] += A.x * B.y;
                acc[ 2] += A.x * B.z; acc[ 3] += A.x * B.w;
                acc[ 4] += A.y * B.x; acc[ 5] += A.y * B.y;
                acc[ 6] += A.y * B.z; acc[ 7] += A.y * B.w;
                acc[ 8] += A.z * B.x; acc[ 9] += A.z * B.y;
                acc[10] += A.z * B.z; acc[11] += A.z * B.w;
                acc[12] += A.w * B.x; acc[13] += A.w * B.y;
                acc[14] += A.w * B.z; acc[15] += A.w * B.w;
            }

            const float sl = RSQ[l] * invn;
            const float so = sl * SQRT2;
            float* fb = F + sel * FEAT_L;

            if (ta < tb) {
                #pragma unroll
                for (int r = 0; r < 4; ++r) {
                    int a  = ta * 4 + r;
                    int p0 = 64 + a * (127 - a) / 2 + (tb * 4 - a - 1);
                    #pragma unroll
                    for (int c = 0; c < 4; ++c)
                        fb[p0 + c] = acc[r * 4 + c] * so;
                }
            } else {   // diagonal tile
                #pragma unroll
                for (int r = 0; r < 4; ++r) {
                    int a = ta * 4 + r;
                    #pragma unroll
                    for (int c = 0; c < 4; ++c) {
                        int b = ta * 4 + c;
                        if (c == r)
                            fb[a] = acc[r * 4 + c] * sl;
                        else if (c > r)
                            fb[64 + a * (127 - a) / 2 + (b - a - 1)]
                                = acc[r * 4 + c] * so;
                    }
                }
            }
        }
        __syncthreads();

        // coalesced float4 stream of this phase's features
        {
            const int nvec = nl_p * FEAT_L / 4;          // 1040 or 520
            const float4* Fv = (const float4*)F;
            float4* ov = (float4*)(op + l0 * FEAT_L);
            for (int i = tid; i < nvec; i += NTHREADS)
                ov[i] = Fv[i];
        }
        __syncthreads();
    }
}

extern "C" void kernel_launch(void* const* d_in, const int* in_sizes, int n_in,
                              void* d_out, int out_size)
{
    const float* se0 = (const float*)d_in[0];
    const float* se1 = (const float*)d_in[1];
    const float* se2 = (const float*)d_in[2];
    const float* se3 = (const float*)d_in[3];
    const float* se4 = (const float*)d_in[4];
    const float* se5 = (const float*)d_in[5];
    const float* se6 = (const float*)d_in[6];
    float* out = (float*)d_out;

    powerspectrum_kernel<<<NJ, NTHREADS, SMEM_BYTES>>>(se0, se1, se2, se3,
                                                       se4, se5, se6, out);
}

// round 6
// speedup vs baseline: 2.1631x; 1.0348x over previous
#include <cuda_runtime.h>

// PowerSpectrum, R6: instruction-count attack.
//  - closed-form task -> (ta,tb) decode (exact fp32 sqrt at boundaries)
//  - SOFF[l] = 68*l*l (no dynamically indexed const arrays)
//  - per-l template-specialized, fully unrolled Gram inner loop
//  - direct register -> gmem streaming epilogue (__stcs), no feature smem
//
// Per env j: for l = 0..6, G_l = S_l S_l^T / sqrt(2l+1), S_l: [64, 2l+1].
// features = concat_l [ diag(G_l) (64) ; sqrt(2)*triu(G_l,1) (2016) ] (14560)
// out = features / max(||features||, 1e-12)

#define NJ       8192
#define NA       64
#define NL       7
#define FEAT_L   2080
#define NDIM     14560
#define TILES_L  136
#define NTASK    (NL * TILES_L)   // 952
#define NTHREADS 256
#define STRIDE   68               // k-row stride in floats

#define S_FLOATS 3332             // 49 * 68
#define SMEM_BYTES (S_FLOATS * 4) // 13328

__device__ __forceinline__ float tile16(const float4& A, const float4& B,
                                        float* acc)
{
    acc[ 0] += A.x * B.x; acc[ 1] += A.x * B.y;
    acc[ 2] += A.x * B.z; acc[ 3] += A.x * B.w;
    acc[ 4] += A.y * B.x; acc[ 5] += A.y * B.y;
    acc[ 6] += A.y * B.z; acc[ 7] += A.y * B.w;
    acc[ 8] += A.z * B.x; acc[ 9] += A.z * B.y;
    acc[10] += A.z * B.z; acc[11] += A.z * B.w;
    acc[12] += A.w * B.x; acc[13] += A.w * B.y;
    acc[14] += A.w * B.z; acc[15] += A.w * B.w;
    return 0.0f;
}

template<int K>
__device__ __forceinline__ void gram_tile(const float* __restrict__ Sl,
                                          int ta, int tb, float* acc)
{
    const float* pa = Sl + ta * 4;
    const float* pb = Sl + tb * 4;
    #pragma unroll
    for (int k = 0; k < K; ++k) {
        float4 A = *(const float4*)(pa + k * STRIDE);  // warp broadcast
        float4 B = *(const float4*)(pb + k * STRIDE);  // conflict-free
        tile16(A, B, acc);
    }
}

__global__ __launch_bounds__(NTHREADS, 4)
void powerspectrum_kernel(const float* __restrict__ se0,
                          const float* __restrict__ se1,
                          const float* __restrict__ se2,
                          const float* __restrict__ se3,
                          const float* __restrict__ se4,
                          const float* __restrict__ se5,
                          const float* __restrict__ se6,
                          float* __restrict__ out)
{
    const float SQRT2 = 1.4142135623730951f;
    // cumulative K*(K+1)/2 for the norm pair tasks
    const int PAIR_OFF[NL + 1] = {0, 1, 7, 22, 50, 95, 161, 252};

    extern __shared__ float dyn[];
    float* S = dyn;                         // k-major: S[68*l*l + k*68 + a]
    __shared__ float red[8];
    __shared__ float s_invn;

    const int j   = blockIdx.x;
    const int tid = threadIdx.x;
    const int lane = tid & 31;
    const int wid  = tid >> 5;

    // ---- stage inputs (coalesced gmem read, k-major transposed smem write) --
    {
        const float* ses[NL] = {se0, se1, se2, se3, se4, se5, se6};
        #pragma unroll
        for (int l = 0; l < NL; ++l) {
            const int K    = 2 * l + 1;
            const int soff = 68 * l * l;
            const float* g = ses[l] + (size_t)j * (NA * K);
            for (int idx = tid; idx < NA * K; idx += NTHREADS) {
                int a = idx / K;
                int k = idx - a * K;
                S[soff + k * STRIDE + a] = __ldcs(&g[idx]);
            }
        }
    }
    __syncthreads();

    // ---- norm via ||S^T S||_F^2: 252 (l, k1<=k2) dot tasks over a=0..63 ----
    float partial = 0.0f;
    if (tid < PAIR_OFF[NL]) {
        int l = 0;
        #pragma unroll
        for (int q = 1; q < NL; ++q)
            if (tid >= PAIR_OFF[q]) l = q;
        int t = tid - PAIR_OFF[l];
        const int K = 2 * l + 1;
        int k1 = 0;
        while (t >= K - k1) { t -= K - k1; ++k1; }
        int k2 = k1 + t;

        const float4* r1 = (const float4*)(S + 68 * l * l + k1 * STRIDE);
        const float4* r2 = (const float4*)(S + 68 * l * l + k2 * STRIDE);
        float dot = 0.0f;
        #pragma unroll
        for (int q = 0; q < NA / 4; ++q) {
            float4 x = r1[q], y = r2[q];
            dot += x.x * y.x + x.y * y.y + x.z * y.z + x.w * y.w;
        }
        float w = (k1 == k2 ? 1.0f : 2.0f) / (float)(2 * l + 1);
        partial = w * dot * dot;
    }
    // warp reduce, then cross-warp via smem
    #pragma unroll
    for (int s = 16; s > 0; s >>= 1)
        partial += __shfl_xor_sync(0xffffffffu, partial, s);
    if (lane == 0) red[wid] = partial;
    __syncthreads();
    if (tid == 0) {
        float tot = 0.0f;
        #pragma unroll
        for (int w = 0; w < 8; ++w) tot += red[w];
        s_invn = 1.0f / fmaxf(sqrtf(tot), 1e-12f);
    }
    __syncthreads();
    const float invn = s_invn;

    // ---- Gram tiles: compute + direct streaming scatter ----
    float* op = out + (size_t)j * NDIM;

    #pragma unroll
    for (int it = 0; it < 4; ++it) {
        int task = tid + it * NTHREADS;
        if (task >= NTASK) break;

        int l = task / TILES_L;            // mul-shift
        int t = task - l * TILES_L;
        // closed-form triu 16x16 tile decode (boundaries exact in fp32)
        int ta = (int)(16.5f - __fsqrt_rn(272.25f - 2.0f * (float)t));
        int tb = ta + t - (ta * (33 - ta)) / 2;

        const float* Sl = S + 68 * l * l;
        float acc[16];
        #pragma unroll
        for (int i = 0; i < 16; ++i) acc[i] = 0.0f;

        switch (l) {
            case 0: gram_tile< 1>(Sl, ta, tb, acc); break;
            case 1: gram_tile< 3>(Sl, ta, tb, acc); break;
            case 2: gram_tile< 5>(Sl, ta, tb, acc); break;
            case 3: gram_tile< 7>(Sl, ta, tb, acc); break;
            case 4: gram_tile< 9>(Sl, ta, tb, acc); break;
            case 5: gram_tile<11>(Sl, ta, tb, acc); break;
            case 6: gram_tile<13>(Sl, ta, tb, acc); break;
        }

        const float sl = __frsqrt_rn((float)(2 * l + 1)) * invn;
        const float so = sl * SQRT2;
        float* ob = op + l * FEAT_L;

        if (ta < tb) {
            #pragma unroll
            for (int r = 0; r < 4; ++r) {
                int a = ta * 4 + r;
                float* p = ob + 64 + a * (127 - a) / 2 + (tb * 4 - a - 1);
                #pragma unroll
                for (int c = 0; c < 4; ++c)
                    __stcs(p + c, acc[r * 4 + c] * so);
            }
        } else {   // diagonal tile
            #pragma unroll
            for (int r = 0; r < 4; ++r) {
                int a = ta * 4 + r;
                __stcs(ob + a, acc[r * 4 + r] * sl);
                float* p = ob + 64 + a * (127 - a) / 2 - a - 1;
                #pragma unroll
                for (int c = 0; c < 4; ++c)
                    if (c > r)
                        __stcs(p + ta * 4 + c, acc[r * 4 + c] * so);
            }
        }
    }
}

extern "C" void kernel_launch(void* const* d_in, const int* in_sizes, int n_in,
                              void* d_out, int out_size)
{
    const float* se0 = (const float*)d_in[0];
    const float* se1 = (const float*)d_in[1];
    const float* se2 = (const float*)d_in[2];
    const float* se3 = (const float*)d_in[3];
    const float* se4 = (const float*)d_in[4];
    const float* se5 = (const float*)d_in[5];
    const float* se6 = (const float*)d_in[6];
    float* out = (float*)d_out;

    powerspectrum_kernel<<<NJ, NTHREADS, SMEM_BYTES>>>(se0, se1, se2, se3,
                                                       se4, se5, se6, out);
}

// round 7
// speedup vs baseline: 2.6019x; 1.2029x over previous
#include <cuda_runtime.h>

// PowerSpectrum, R7: row-slab decomposition matched to the packed-triu output
// layout. A warp owns 4 Gram rows x the needed column range; lanes own column
// pairs, so stores are segment-coalesced (fixed row -> contiguous b). Narrow
// slabs are packed in complementary pairs (ta, 16-ta') to keep warps full.
//
// Per env j: for l = 0..6, G_l = S_l S_l^T / sqrt(2l+1), S_l: [64, 2l+1].
// features = concat_l [ diag(G_l) (64) ; sqrt(2)*triu(G_l,1) (2016) ] (14560)
// out = features / max(||features||, 1e-12)

#define NJ       8192
#define NA       64
#define NL       7
#define FEAT_L   2080
#define NDIM     14560
#define NTHREADS 256
#define STRIDE   68               // k-row stride in floats
#define S_FLOATS 3332             // 49 * 68
#define SMEM_BYTES (S_FLOATS * 4) // 13328
#define NWTASK   63               // 7 l * 9 packed slab tasks

template<int K>
__device__ __forceinline__ void slab_gram(const float* __restrict__ base,
                                          int rowbase, int b, float* acc)
{
    #pragma unroll
    for (int k = 0; k < K; ++k) {
        const float* row = base + k * STRIDE;
        float4 A = *(const float4*)(row + rowbase);   // warp broadcast (<=2 addrs)
        float2 B = *(const float2*)(row + b);         // contiguous, conflict-free
        acc[0] += A.x * B.x; acc[1] += A.x * B.y;
        acc[2] += A.y * B.x; acc[3] += A.y * B.y;
        acc[4] += A.z * B.x; acc[5] += A.z * B.y;
        acc[6] += A.w * B.x; acc[7] += A.w * B.y;
    }
}

__global__ __launch_bounds__(NTHREADS, 5)
void powerspectrum_kernel(const float* __restrict__ se0,
                          const float* __restrict__ se1,
                          const float* __restrict__ se2,
                          const float* __restrict__ se3,
                          const float* __restrict__ se4,
                          const float* __restrict__ se5,
                          const float* __restrict__ se6,
                          float* __restrict__ out)
{
    const float SQRT2 = 1.4142135623730951f;
    const int PAIR_OFF[NL + 1] = {0, 1, 7, 22, 50, 95, 161, 252};

    extern __shared__ float dyn[];
    float* S = dyn;                        // k-major: S[68*l*l + k*68 + a]
    __shared__ float red[8];
    __shared__ float s_invn;

    const int j    = blockIdx.x;
    const int tid  = threadIdx.x;
    const int lane = tid & 31;
    const int wid  = tid >> 5;

    // ---- stage inputs (coalesced gmem read, k-major transposed smem write) --
    {
        const float* ses[NL] = {se0, se1, se2, se3, se4, se5, se6};
        #pragma unroll
        for (int l = 0; l < NL; ++l) {
            const int K    = 2 * l + 1;
            const int soff = 68 * l * l;
            const float* g = ses[l] + (size_t)j * (NA * K);
            for (int idx = tid; idx < NA * K; idx += NTHREADS) {
                int a = idx / K;
                int k = idx - a * K;
                S[soff + k * STRIDE + a] = __ldcs(&g[idx]);
            }
        }
    }
    __syncthreads();

    // ---- norm via ||S^T S||_F^2: 252 (l, k1<=k2) dot tasks over a=0..63 ----
    float partial = 0.0f;
    if (tid < PAIR_OFF[NL]) {
        int l = 0;
        #pragma unroll
        for (int q = 1; q < NL; ++q)
            if (tid >= PAIR_OFF[q]) l = q;
        int t = tid - PAIR_OFF[l];
        const int K = 2 * l + 1;
        int k1 = 0;
        while (t >= K - k1) { t -= K - k1; ++k1; }
        int k2 = k1 + t;

        const float4* r1 = (const float4*)(S + 68 * l * l + k1 * STRIDE);
        const float4* r2 = (const float4*)(S + 68 * l * l + k2 * STRIDE);
        float dot = 0.0f;
        #pragma unroll
        for (int q = 0; q < NA / 4; ++q) {
            float4 x = r1[q], y = r2[q];
            dot += x.x * y.x + x.y * y.y + x.z * y.z + x.w * y.w;
        }
        float w = (k1 == k2 ? 1.0f : 2.0f) / (float)(2 * l + 1);
        partial = w * dot * dot;
    }
    #pragma unroll
    for (int s = 16; s > 0; s >>= 1)
        partial += __shfl_xor_sync(0xffffffffu, partial, s);
    if (lane == 0) red[wid] = partial;
    __syncthreads();
    if (tid == 0) {
        float tot = 0.0f;
        #pragma unroll
        for (int w = 0; w < 8; ++w) tot += red[w];
        s_invn = 1.0f / fmaxf(sqrtf(tot), 1e-12f);
    }
    __syncthreads();
    const float invn = s_invn;

    // ---- row-slab Gram tasks: 9 packed tasks per l, 63 total, 8 warps ------
    float* op = out + (size_t)j * NDIM;

    for (int t = wid; t < NWTASK; t += 8) {
        int l   = t / 9;
        int sub = t - l * 9;
        // packed segment pairs: widths 64-4*ta; (0),(8) single, (s-1, 17-s) pairs
        int taA, taB;
        if (sub == 0)      { taA = 0; taB = 16; }   // taB=16 -> width 0
        else if (sub == 1) { taA = 8; taB = 16; }
        else               { taA = sub - 1; taB = 17 - sub; }

        const int wA = 64 - 4 * taA;
        const int p  = 2 * lane;
        const bool inA = p < wA;
        int rowbase = inA ? 4 * taA : 4 * taB;
        int b       = inA ? (4 * taA + p) : (4 * taB + (p - wA));
        const bool active = b < 64;
        if (!active) { rowbase = 0; b = 0; }

        const float* base = S + 68 * l * l;
        float acc[8];
        #pragma unroll
        for (int i = 0; i < 8; ++i) acc[i] = 0.0f;

        switch (l) {
            case 0: slab_gram< 1>(base, rowbase, b, acc); break;
            case 1: slab_gram< 3>(base, rowbase, b, acc); break;
            case 2: slab_gram< 5>(base, rowbase, b, acc); break;
            case 3: slab_gram< 7>(base, rowbase, b, acc); break;
            case 4: slab_gram< 9>(base, rowbase, b, acc); break;
            case 5: slab_gram<11>(base, rowbase, b, acc); break;
            case 6: slab_gram<13>(base, rowbase, b, acc); break;
        }

        const float sl = __frsqrt_rn((float)(2 * l + 1)) * invn;
        const float so = sl * SQRT2;
        float* ob = op + l * FEAT_L;

        if (active) {
            #pragma unroll
            for (int r = 0; r < 4; ++r) {
                int a = rowbase + r;
                int rowoff = 64 + (a * (127 - a)) / 2 - a - 1;  // + b
                #pragma unroll
                for (int c = 0; c < 2; ++c) {
                    int bb = b + c;
                    float v = acc[r * 2 + c];
                    if (bb > a)
                        __stcs(ob + rowoff + bb, v * so);   // triu, coalesced in b
                    else if (bb == a)
                        __stcs(ob + a, v * sl);             // diag
                }
            }
        }
    }
}

extern "C" void kernel_launch(void* const* d_in, const int* in_sizes, int n_in,
                              void* d_out, int out_size)
{
    const float* se0 = (const float*)d_in[0];
    const float* se1 = (const float*)d_in[1];
    const float* se2 = (const float*)d_in[2];
    const float* se3 = (const float*)d_in[3];
    const float* se4 = (const float*)d_in[4];
    const float* se5 = (const float*)d_in[5];
    const float* se6 = (const float*)d_in[6];
    float* out = (float*)d_out;

    powerspectrum_kernel<<<NJ, NTHREADS, SMEM_BYTES>>>(se0, se1, se2, se3,
                                                       se4, se5, se6, out);
}

// round 8
// speedup vs baseline: 2.6184x; 1.0063x over previous
#include <cuda_runtime.h>

// PowerSpectrum, R8: full-sector stores.
//  - diag(G) computed/stored in its own tiny phase -> slab tasks write only
//    strict-triu runs (no diag predicates in the hot epilogue)
//  - parity-aware epilogue: even row offset -> direct float2 STG.64;
//    odd -> shfl_down re-pairing (v1_i, v0_{i+1}) so stores stay 8B-aligned
//  - every 32B sector written once, by one instruction, fully
//
// Per env j: for l = 0..6, G_l = S_l S_l^T / sqrt(2l+1), S_l: [64, 2l+1].
// features = concat_l [ diag(G_l) (64) ; sqrt(2)*triu(G_l,1) (2016) ] (14560)
// out = features / max(||features||, 1e-12)

#define NJ       8192
#define NA       64
#define NL       7
#define FEAT_L   2080
#define NDIM     14560
#define NTHREADS 256
#define STRIDE   68               // k-row stride in floats
#define S_FLOATS 3332             // 49 * 68
#define SMEM_BYTES (S_FLOATS * 4) // 13328
#define NWTASK   63               // 7 l * 9 packed slab tasks
#define NDIAG    (NL * NA)        // 448

template<int K>
__device__ __forceinline__ void slab_gram(const float* __restrict__ base,
                                          int rowbase, int b, float* acc)
{
    #pragma unroll
    for (int k = 0; k < K; ++k) {
        const float* row = base + k * STRIDE;
        float4 A = *(const float4*)(row + rowbase);   // warp broadcast (<=2 addrs)
        float2 B = *(const float2*)(row + b);         // contiguous, conflict-free
        acc[0] += A.x * B.x; acc[1] += A.x * B.y;
        acc[2] += A.y * B.x; acc[3] += A.y * B.y;
        acc[4] += A.z * B.x; acc[5] += A.z * B.y;
        acc[6] += A.w * B.x; acc[7] += A.w * B.y;
    }
}

__global__ __launch_bounds__(NTHREADS, 5)
void powerspectrum_kernel(const float* __restrict__ se0,
                          const float* __restrict__ se1,
                          const float* __restrict__ se2,
                          const float* __restrict__ se3,
                          const float* __restrict__ se4,
                          const float* __restrict__ se5,
                          const float* __restrict__ se6,
                          float* __restrict__ out)
{
    const float SQRT2 = 1.4142135623730951f;
    const int PAIR_OFF[NL + 1] = {0, 1, 7, 22, 50, 95, 161, 252};

    extern __shared__ float dyn[];
    float* S = dyn;                        // k-major: S[68*l*l + k*68 + a]
    __shared__ float red[8];
    __shared__ float s_invn;

    const int j    = blockIdx.x;
    const int tid  = threadIdx.x;
    const int lane = tid & 31;
    const int wid  = tid >> 5;

    // ---- stage inputs (coalesced gmem read, k-major transposed smem write) --
    {
        const float* ses[NL] = {se0, se1, se2, se3, se4, se5, se6};
        #pragma unroll
        for (int l = 0; l < NL; ++l) {
            const int K    = 2 * l + 1;
            const int soff = 68 * l * l;
            const float* g = ses[l] + (size_t)j * (NA * K);
            for (int idx = tid; idx < NA * K; idx += NTHREADS) {
                int a = idx / K;
                int k = idx - a * K;
                S[soff + k * STRIDE + a] = __ldcs(&g[idx]);
            }
        }
    }
    __syncthreads();

    // ---- norm via ||S^T S||_F^2: 252 (l, k1<=k2) dot tasks over a=0..63 ----
    float partial = 0.0f;
    if (tid < PAIR_OFF[NL]) {
        int l = 0;
        #pragma unroll
        for (int q = 1; q < NL; ++q)
            if (tid >= PAIR_OFF[q]) l = q;
        int t = tid - PAIR_OFF[l];
        const int K = 2 * l + 1;
        int k1 = 0;
        while (t >= K - k1) { t -= K - k1; ++k1; }
        int k2 = k1 + t;

        const float4* r1 = (const float4*)(S + 68 * l * l + k1 * STRIDE);
        const float4* r2 = (const float4*)(S + 68 * l * l + k2 * STRIDE);
        float dot = 0.0f;
        #pragma unroll
        for (int q = 0; q < NA / 4; ++q) {
            float4 x = r1[q], y = r2[q];
            dot += x.x * y.x + x.y * y.y + x.z * y.z + x.w * y.w;
        }
        float w = (k1 == k2 ? 1.0f : 2.0f) / (float)(2 * l + 1);
        partial = w * dot * dot;
    }
    #pragma unroll
    for (int s = 16; s > 0; s >>= 1)
        partial += __shfl_xor_sync(0xffffffffu, partial, s);
    if (lane == 0) red[wid] = partial;
    __syncthreads();
    if (tid == 0) {
        float tot = 0.0f;
        #pragma unroll
        for (int w = 0; w < 8; ++w) tot += red[w];
        s_invn = 1.0f / fmaxf(sqrtf(tot), 1e-12f);
    }
    __syncthreads();
    const float invn = s_invn;

    float* op = out + (size_t)j * NDIM;

    // ---- diag phase: 448 (l,a) self-dots, coalesced scalar stores ----------
    for (int t = tid; t < NDIAG; t += NTHREADS) {
        int l = t >> 6;
        int a = t & 63;
        const int K = 2 * l + 1;
        const float* p = S + 68 * l * l + a;
        float d = 0.0f;
        for (int k = 0; k < K; ++k) {
            float v = p[k * STRIDE];
            d += v * v;
        }
        __stcs(op + l * FEAT_L + a, d * __frsqrt_rn((float)K) * invn);
    }

    // ---- strict-triu row-slab tasks: 9 packed per l, 63 total, 8 warps -----
    for (int t = wid; t < NWTASK; t += 8) {
        int l   = t / 9;
        int sub = t - l * 9;
        // packed segment pairs: widths 64-4*ta; (0),(8) single, (s-1,17-s) pairs
        int taA, taB;
        if (sub == 0)      { taA = 0; taB = 16; }   // taB=16 -> width 0
        else if (sub == 1) { taA = 8; taB = 16; }
        else               { taA = sub - 1; taB = 17 - sub; }

        const int wA  = 64 - 4 * taA;
        const int p   = 2 * lane;
        const bool inA = p < wA;
        int rowbase = inA ? 4 * taA : 4 * taB;
        int b       = inA ? (4 * taA + p) : (4 * taB + (p - wA));
        const bool active = b < 64;
        const bool islast = inA ? (lane == (wA >> 1) - 1) : (lane == 31);
        if (!active) { rowbase = 0; b = 0; }

        const float* base = S + 68 * l * l;
        float acc[8];
        #pragma unroll
        for (int i = 0; i < 8; ++i) acc[i] = 0.0f;

        switch (l) {
            case 0: slab_gram< 1>(base, rowbase, b, acc); break;
            case 1: slab_gram< 3>(base, rowbase, b, acc); break;
            case 2: slab_gram< 5>(base, rowbase, b, acc); break;
            case 3: slab_gram< 7>(base, rowbase, b, acc); break;
            case 4: slab_gram< 9>(base, rowbase, b, acc); break;
            case 5: slab_gram<11>(base, rowbase, b, acc); break;
            case 6: slab_gram<13>(base, rowbase, b, acc); break;
        }

        const float so = __frsqrt_rn((float)(2 * l + 1)) * invn * SQRT2;
        float* ob = op + l * FEAT_L;

        #pragma unroll
        for (int r = 0; r < 4; ++r) {
            const int a      = rowbase + r;
            const int rowoff = 64 + (a * (127 - a)) / 2 - a - 1;  // + b -> gmem idx
            float v0 = acc[r * 2]     * so;
            float v1 = acc[r * 2 + 1] * so;
            float nv0 = __shfl_down_sync(0xffffffffu, v0, 1);     // next lane's v0

            if (!active) continue;

            if ((rowoff & 1) == 0) {
                // pair (b, b+1) is 8B-aligned
                if (b > a) {
                    *(float2*)(ob + rowoff + b) = make_float2(v0, v1);
                } else if (b == a) {
                    __stcs(ob + rowoff + b + 1, v1);       // element a+1
                }
            } else {
                // aligned pairs are (b+1, b+2) = (v1, next v0)
                if (b + 1 > a && !islast) {
                    *(float2*)(ob + rowoff + b + 1) = make_float2(v1, nv0);
                } else if (b + 1 == a && a < 63) {
                    __stcs(ob + rowoff + b + 2, nv0);      // element a+1
                }
                if (islast && a < 63) {
                    __stcs(ob + rowoff + 63, v1);          // tail element 63
                }
            }
        }
    }
}

extern "C" void kernel_launch(void* const* d_in, const int* in_sizes, int n_in,
                              void* d_out, int out_size)
{
    const float* se0 = (const float*)d_in[0];
    const float* se1 = (const float*)d_in[1];
    const float* se2 = (const float*)d_in[2];
    const float* se3 = (const float*)d_in[3];
    const float* se4 = (const float*)d_in[4];
    const float* se5 = (const float*)d_in[5];
    const float* se6 = (const float*)d_in[6];
    float* out = (float*)d_out;

    powerspectrum_kernel<<<NJ, NTHREADS, SMEM_BYTES>>>(se0, se1, se2, se3,
                                                       se4, se5, se6, out);
}

// round 10
// speedup vs baseline: 2.8925x; 1.1047x over previous
#include <cuda_runtime.h>

// PowerSpectrum, R9: issue-count attack.
//  - packed f32x2 FFMA (FFMA2) in the Gram loop; acc packed along rows so A
//    is natively u64 pairs; only B.x/B.y need dup-movs
//  - 8-row x 2-col lane slabs: 13 instr / 16 FMA (was 10/8); 35 warp-tasks
//  - epilogue: store parity is compile-time per row (rowbase % 8 == 0);
//    packed scale; unpack is register aliasing
//
// Per env j: for l = 0..6, G_l = S_l S_l^T / sqrt(2l+1), S_l: [64, 2l+1].
// features = concat_l [ diag(G_l) (64) ; sqrt(2)*triu(G_l,1) (2016) ] (14560)
// out = features / max(||features||, 1e-12)

#define NJ       8192
#define NA       64
#define NL       7
#define FEAT_L   2080
#define NDIM     14560
#define NTHREADS 256
#define STRIDE   68               // k-row stride in floats
#define S_FLOATS 3332             // 49 * 68
#define SMEM_BYTES (S_FLOATS * 4) // 13328
#define NWTASK   35               // 7 l * 5 packed 8-row slab tasks
#define NDIAG    (NL * NA)        // 448

typedef unsigned long long u64;

__device__ __forceinline__ u64 dup2(float x) {
    u64 r;
    asm("mov.b64 %0, {%1, %1};" : "=l"(r) : "f"(x));
    return r;
}
__device__ __forceinline__ void ffma2(u64& d, u64 a, u64 b) {
    asm("fma.rn.f32x2 %0, %1, %2, %0;" : "+l"(d) : "l"(a), "l"(b));
}
__device__ __forceinline__ void mul2(u64& d, u64 s) {
    asm("mul.rn.f32x2 %0, %0, %1;" : "+l"(d) : "l"(s));
}
__device__ __forceinline__ float2 unpack2(u64 v) {
    float lo, hi;
    asm("mov.b64 {%0, %1}, %2;" : "=f"(lo), "=f"(hi) : "l"(v));
    return make_float2(lo, hi);
}

// acc[2*rp + c] = packed {G[2rp][b+c], G[2rp+1][b+c]}, rp = 0..3
template<int K>
__device__ __forceinline__ void slab_gram8(const float* __restrict__ rowA,
                                           const float* __restrict__ rowB,
                                           u64* acc)
{
    #pragma unroll
    for (int k = 0; k < K; ++k) {
        ulonglong2 A0 = *(const ulonglong2*)(rowA + k * STRIDE);     // rows 0-3
        ulonglong2 A1 = *(const ulonglong2*)(rowA + k * STRIDE + 4); // rows 4-7
        float2 B = *(const float2*)(rowB + k * STRIDE);
        u64 b0 = dup2(B.x);
        u64 b1 = dup2(B.y);
        ffma2(acc[0], A0.x, b0); ffma2(acc[1], A0.x, b1);   // rows 0,1
        ffma2(acc[2], A0.y, b0); ffma2(acc[3], A0.y, b1);   // rows 2,3
        ffma2(acc[4], A1.x, b0); ffma2(acc[5], A1.x, b1);   // rows 4,5
        ffma2(acc[6], A1.y, b0); ffma2(acc[7], A1.y, b1);   // rows 6,7
    }
}

template<int K>
__device__ __forceinline__ float selfdot(const float* __restrict__ p) {
    float d = 0.0f;
    #pragma unroll
    for (int k = 0; k < K; ++k) { float v = p[k * STRIDE]; d += v * v; }
    return d;
}

__global__ __launch_bounds__(NTHREADS, 4)
void powerspectrum_kernel(const float* __restrict__ se0,
                          const float* __restrict__ se1,
                          const float* __restrict__ se2,
                          const float* __restrict__ se3,
                          const float* __restrict__ se4,
                          const float* __restrict__ se5,
                          const float* __restrict__ se6,
                          float* __restrict__ out)
{
    const float SQRT2 = 1.4142135623730951f;
    const int PAIR_OFF[NL + 1] = {0, 1, 7, 22, 50, 95, 161, 252};

    extern __shared__ float dyn[];
    float* S = dyn;                        // k-major: S[68*l*l + k*68 + a]
    __shared__ float red[8];
    __shared__ float s_invn;

    const int j    = blockIdx.x;
    const int tid  = threadIdx.x;
    const int lane = tid & 31;
    const int wid  = tid >> 5;

    // ---- stage inputs: float4 gmem reads, k-major transposed smem writes ---
    {
        const float* ses[NL] = {se0, se1, se2, se3, se4, se5, se6};
        #pragma unroll
        for (int l = 0; l < NL; ++l) {
            const int K    = 2 * l + 1;
            const int soff = 68 * l * l;
            const float4* g4 = (const float4*)(ses[l] + (size_t)j * (NA * K));
            const int n4 = NA * K / 4;
            for (int q = tid; q < n4; q += NTHREADS) {
                float4 v = __ldcs(&g4[q]);
                int idx = 4 * q;
                int a = idx / K;
                int k = idx - a * K;
                float vv[4] = {v.x, v.y, v.z, v.w};
                #pragma unroll
                for (int i = 0; i < 4; ++i) {
                    S[soff + k * STRIDE + a] = vv[i];
                    if (++k == K) { k = 0; ++a; }
                }
            }
        }
    }
    __syncthreads();

    // ---- norm via ||S^T S||_F^2: 252 (l, k1<=k2) dot tasks over a=0..63 ----
    float partial = 0.0f;
    if (tid < PAIR_OFF[NL]) {
        int l = 0;
        #pragma unroll
        for (int q = 1; q < NL; ++q)
            if (tid >= PAIR_OFF[q]) l = q;
        int t = tid - PAIR_OFF[l];
        const int K = 2 * l + 1;
        int k1 = 0;
        while (t >= K - k1) { t -= K - k1; ++k1; }
        int k2 = k1 + t;

        const float4* r1 = (const float4*)(S + 68 * l * l + k1 * STRIDE);
        const float4* r2 = (const float4*)(S + 68 * l * l + k2 * STRIDE);
        float dot = 0.0f;
        #pragma unroll
        for (int q = 0; q < NA / 4; ++q) {
            float4 x = r1[q], y = r2[q];
            dot += x.x * y.x + x.y * y.y + x.z * y.z + x.w * y.w;
        }
        float w = (k1 == k2 ? 1.0f : 2.0f) / (float)(2 * l + 1);
        partial = w * dot * dot;
    }
    #pragma unroll
    for (int s = 16; s > 0; s >>= 1)
        partial += __shfl_xor_sync(0xffffffffu, partial, s);
    if (lane == 0) red[wid] = partial;
    __syncthreads();
    if (tid == 0) {
        float tot = 0.0f;
        #pragma unroll
        for (int w = 0; w < 8; ++w) tot += red[w];
        s_invn = 1.0f / fmaxf(sqrtf(tot), 1e-12f);
    }
    __syncthreads();
    const float invn = s_invn;

    float* op = out + (size_t)j * NDIM;

    // ---- diag phase: 448 (l,a) self-dots, coalesced scalar stores ----------
    for (int t = tid; t < NDIAG; t += NTHREADS) {
        int l = t >> 6;
        int a = t & 63;
        const float* p = S + 68 * l * l + a;
        float d;
        switch (l) {
            case 0: d = selfdot< 1>(p); break;
            case 1: d = selfdot< 3>(p); break;
            case 2: d = selfdot< 5>(p); break;
            case 3: d = selfdot< 7>(p); break;
            case 4: d = selfdot< 9>(p); break;
            case 5: d = selfdot<11>(p); break;
            default: d = selfdot<13>(p); break;
        }
        __stcs(op + l * FEAT_L + a,
               d * __frsqrt_rn((float)(2 * l + 1)) * invn);
    }

    // ---- strict-triu 8-row slab tasks: 5 packed per l, 35 total ------------
    for (int t = wid; t < NWTASK; t += 8) {
        int l   = t / 5;
        int sub = t - l * 5;
        // slabs s have rows [8s,8s+8), col-pairs b=8s..62, lane width 32-4s.
        // packing: {0}, {1,7}, {2,6}, {3,5}, {4}
        const int sA = sub;
        const int sB = 8 - sub;
        const int nA = 32 - 4 * sub;
        const int nB = (sub == 4) ? 0 : 4 * sub;   // sub=0 -> 0

        const bool inA    = lane < nA;
        const bool active = lane < nA + nB;
        int rowbase = inA ? 8 * sA : 8 * sB;
        int lanep   = inA ? lane : lane - nA;
        int b       = rowbase + 2 * lanep;
        const bool islast = (lane == nA - 1) || (lane == nA + nB - 1);
        if (!active) { rowbase = 0; b = 0; }

        const float* base = S + 68 * l * l;
        const float* rowA = base + rowbase;
        const float* rowB = base + b;

        u64 acc[8];
        #pragma unroll
        for (int i = 0; i < 8; ++i) acc[i] = 0ull;

        switch (l) {
            case 0: slab_gram8< 1>(rowA, rowB, acc); break;
            case 1: slab_gram8< 3>(rowA, rowB, acc); break;
            case 2: slab_gram8< 5>(rowA, rowB, acc); break;
            case 3: slab_gram8< 7>(rowA, rowB, acc); break;
            case 4: slab_gram8< 9>(rowA, rowB, acc); break;
            case 5: slab_gram8<11>(rowA, rowB, acc); break;
            case 6: slab_gram8<13>(rowA, rowB, acc); break;
        }

        // packed scale by sqrt(2)/sqrt(2l+1)/norm
        const float so = __frsqrt_rn((float)(2 * l + 1)) * invn * SQRT2;
        const u64 so2 = dup2(so);
        #pragma unroll
        for (int i = 0; i < 8; ++i) mul2(acc[i], so2);

        float2 u[8];
        #pragma unroll
        for (int i = 0; i < 8; ++i) u[i] = unpack2(acc[i]);  // reg aliasing

        float* ob = op + l * FEAT_L;

        // rowoff parity pattern vs a (period 4): a%4 = 0,1 -> odd; 2,3 -> even
        // rowbase % 8 == 0, so parity is compile-time per r.
        #pragma unroll
        for (int r = 0; r < 8; ++r) {
            const int rp = r >> 1;
            const float v0 = (r & 1) ? u[2 * rp].y     : u[2 * rp].x;
            const float v1 = (r & 1) ? u[2 * rp + 1].y : u[2 * rp + 1].x;
            const int a      = rowbase + r;
            const int rowoff = 64 + ((a * (127 - a)) >> 1) - a - 1;

            if ((r & 3) >= 2) {
                // even rowoff: pair (b, b+1) is 8B-aligned
                if (active) {
                    if (b > a) {
                        *(float2*)(ob + rowoff + b) = make_float2(v0, v1);
                    } else if ((r & 1) == 0 && b == a) {
                        __stcs(ob + rowoff + a + 1, v1);   // element a+1
                    }
                }
            } else {
                // odd rowoff: aligned pairs are (b+1, b+2) = (v1, next v0)
                const float nv0 = __shfl_down_sync(0xffffffffu, v0, 1);
                if (active) {
                    if (b >= a && !islast) {
                        *(float2*)(ob + rowoff + b + 1) = make_float2(v1, nv0);
                    } else if ((r & 1) == 1 && b + 1 == a) {
                        __stcs(ob + rowoff + b + 2, nv0);  // element a+1
                    }
                    if (islast) {
                        __stcs(ob + rowoff + 63, v1);      // tail element 63
                    }
                }
            }
        }
    }
}

extern "C" void kernel_launch(void* const* d_in, const int* in_sizes, int n_in,
                              void* d_out, int out_size)
{
    const float* se0 = (const float*)d_in[0];
    const float* se1 = (const float*)d_in[1];
    const float* se2 = (const float*)d_in[2];
    const float* se3 = (const float*)d_in[3];
    const float* se4 = (const float*)d_in[4];
    const float* se5 = (const float*)d_in[5];
    const float* se6 = (const float*)d_in[6];
    float* out = (float*)d_out;

    powerspectrum_kernel<<<NJ, NTHREADS, SMEM_BYTES>>>(se0, se1, se2, se3,
                                                       se4, se5, se6, out);
}